// round 8
// baseline (speedup 1.0000x reference)
#include <cuda_runtime.h>
#include <math.h>

#define NT   256
#define BSUB 4
#define TT   128
#define DD   256
#define HW   128

__device__ __forceinline__ float tanha(float x) {
    float y; asm("tanh.approx.f32 %0, %1;" : "=f"(y) : "f"(x)); return y;
}
#define FFMA2(acc, a, b) \
    asm("fma.rn.f32x2 %0, %1, %2, %3;" : "=l"(acc) : "l"(a), "l"(b), "l"(acc))
#define ADD2(d, a, b) \
    asm("add.rn.f32x2 %0, %1, %2;" : "=l"(d) : "l"(a), "l"(b))
#define PACK2(d, lo, hi) \
    asm("mov.b64 %0, {%1,%2};" : "=l"(d) : "f"(lo), "f"(hi))
#define UNPACK2(lo, hi, d) \
    asm("mov.b64 {%0,%1}, %2;" : "=f"(lo), "=f"(hi) : "l"(d))

__device__ __forceinline__ float interp_c(float t, const float* __restrict__ row) {
    int i = (int)ceilf(t);
    i = i < 1 ? 1 : (i > DD - 1 ? DD - 1 : i);
    float w = t - (float)(i - 1);
    w = fminf(fmaxf(w, 0.f), 1.f);
    return (1.f - w) * row[i - 1] + w * row[i];
}

__global__ __launch_bounds__(NT, 2)
void ode_kernel(const float* __restrict__ ts, const float* __restrict__ y0,
                const float* __restrict__ latent, const int* __restrict__ length,
                const float* __restrict__ dts, const float* __restrict__ dcs,
                const float* __restrict__ W1, const float* __restrict__ b1,
                const float* __restrict__ W2, const float* __restrict__ b2,
                const float* __restrict__ W3, const float* __restrict__ b3,
                float* __restrict__ out)
{
    extern __shared__ float sm[];
    unsigned long long* h1d = reinterpret_cast<unsigned long long*>(sm); // [128][4] u64
    unsigned long long* pSd = h1d + 512;     // [4 r][8 kg][64] u64 (o-pair partials)
    unsigned long long* b2d = pSd + 2048;    // [64] u64 (b2[k], b2[k+64])
    float* W3t    = reinterpret_cast<float*>(b2d + 64);  // [128][9]
    float* csS    = W3t + 1152;              // [4][256]
    float* tsS    = csS + 1024;              // [128]
    float* Ystage = tsS + 128;               // [4][12]
    float* cS     = Ystage + 48;             // [4]
    float* b3s    = cS + 4;                  // [12]

    const int tid = threadIdx.x;
    const int l   = tid & 31;
    const int kg  = tid >> 5;                // warp 0..7 = k-group for L2
    const int r0  = blockIdx.x * BSUB;
    const int o1  = l + 32 * (kg & 3);       // L1 neuron
    const int e   = kg >> 2;                 // L1 row-pair (rows 2e, 2e+1)

    // ---- one-time setup ----
    for (int i = tid; i < 9 * HW; i += NT) {
        int oo = i >> 7, k = i & 127;
        W3t[k * 9 + oo] = W3[i];
    }
    for (int i = tid; i < BSUB * DD; i += NT) {
        int r = i >> 8;
        csS[i] = dcs[(r0 + r) * DD + (i & 255)];
    }
    if (tid < TT) tsS[tid] = ts[tid];
    if (tid >= 128 && tid < 192) {
        int k = tid - 128;
        PACK2(b2d[k], b2[k], b2[k + 64]);
    }
    if (tid >= 192 && tid < 201) b3s[tid - 192] = b3[tid - 192];

    // ---- register-resident weights ----
    unsigned long long w2p[2][16];           // (W2[o][k], W2[o+64][k]), o = l+32mp
    #pragma unroll
    for (int mp = 0; mp < 2; ++mp) {
        const float* wa = W2 + (l + 32 * mp) * HW + 16 * kg;
        const float* wb = wa + 64 * HW;
        #pragma unroll
        for (int kk = 0; kk < 16; ++kk) PACK2(w2p[mp][kk], wa[kk], wb[kk]);
    }
    unsigned long long w1p[5];
    float w1t, bpre2[2];
    {
        const float* w = W1 + o1 * 43;
        PACK2(w1p[0], w[0], w[1]);
        PACK2(w1p[1], w[2], w[3]);
        PACK2(w1p[2], w[4], w[5]);
        PACK2(w1p[3], w[6], w[7]);
        PACK2(w1p[4], w[8], w[42]);          // (w1_y8, w1_c)
        w1t = w[41];
        #pragma unroll
        for (int rr = 0; rr < 2; ++rr) {
            int r = 2 * e + rr;
            float a = b1[o1];
            const float* lat = latent + (r0 + r) * 32;
            #pragma unroll
            for (int j = 0; j < 32; ++j) a += w[9 + j] * lat[j];
            bpre2[rr] = a;
        }
    }

    // ---- ODE state in L3-warp lane registers ----
    float Ybase_l = 0.f, Yacc_l = 0.f, tendr = 0.f;
    if (kg < BSUB) {
        const int r = kg;
        int len = length[r0 + r];
        int idx = len - 1; if (idx < 0) idx = 0;
        tendr = ts[idx];
        float y0r = y0[r0 + r];
        if (l == 0) out[(r0 + r) * TT] = y0r;
        if (l < 9) {
            Ybase_l = (l == 0) ? y0r : 0.f;
            Yacc_l  = Ybase_l;
            Ystage[r * 12 + l] = Ybase_l;
        }
        if (l == 16) cS[r] = interp_c(ts[0], dcs + (r0 + r) * DD);
    }
    __syncthreads();

    const float A2[4] = {0.f, 0.5f, 0.5f, 1.f};
    const float Wc[4] = {1.f, 2.f, 2.f, 1.f};

    for (int n = 0; n < TT - 1; ++n) {
        float t0  = tsS[n];
        float dtf = (tsS[n + 1] - t0) * 0.5f;      // SUB = 2
        #pragma unroll 1
        for (int sub = 0; sub < 2; ++sub) {
            float tstart = t0 + (float)sub * dtf;
            #pragma unroll
            for (int s = 0; s < 4; ++s) {
                float tt = tstart + A2[s] * dtf;

                // ---- layer 1: neuron o1, rows 2e, 2e+1; store dup-pairs ----
                {
                    float hv[2];
                    #pragma unroll
                    for (int rr = 0; rr < 2; ++rr) {
                        const int r = 2 * e + rr;
                        ulonglong2 ya = *reinterpret_cast<const ulonglong2*>(Ystage + r * 12);
                        ulonglong2 yb = *reinterpret_cast<const ulonglong2*>(Ystage + r * 12 + 4);
                        unsigned long long y8c;
                        PACK2(y8c, Ystage[r * 12 + 8], cS[r]);
                        unsigned long long a2 = 0ull;
                        FFMA2(a2, w1p[0], ya.x);
                        FFMA2(a2, w1p[1], ya.y);
                        FFMA2(a2, w1p[2], yb.x);
                        FFMA2(a2, w1p[3], yb.y);
                        FFMA2(a2, w1p[4], y8c);
                        float lo, hi; UNPACK2(lo, hi, a2);
                        hv[rr] = tanha(fmaf(w1t, tt, bpre2[rr]) + lo + hi);
                    }
                    float4 hq = make_float4(hv[0], hv[0], hv[1], hv[1]);
                    *reinterpret_cast<float4*>(h1d + o1 * 4 + 2 * e) = hq;
                }
                __syncthreads();

                // ---- layer 2: o-pair W2 regs x dup-h, zero packing ----
                {
                    unsigned long long acc00 = 0ull, acc01 = 0ull, acc02 = 0ull, acc03 = 0ull;
                    unsigned long long acc10 = 0ull, acc11 = 0ull, acc12 = 0ull, acc13 = 0ull;
                    const unsigned long long* hk = h1d + 64 * kg;   // k = 16kg + kk
                    #pragma unroll 4
                    for (int kk = 0; kk < 16; ++kk) {
                        ulonglong2 v0 = *reinterpret_cast<const ulonglong2*>(hk + 4 * kk);
                        ulonglong2 v1 = *reinterpret_cast<const ulonglong2*>(hk + 4 * kk + 2);
                        FFMA2(acc00, w2p[0][kk], v0.x);
                        FFMA2(acc01, w2p[0][kk], v0.y);
                        FFMA2(acc02, w2p[0][kk], v1.x);
                        FFMA2(acc03, w2p[0][kk], v1.y);
                        FFMA2(acc10, w2p[1][kk], v0.x);
                        FFMA2(acc11, w2p[1][kk], v0.y);
                        FFMA2(acc12, w2p[1][kk], v1.x);
                        FFMA2(acc13, w2p[1][kk], v1.y);
                    }
                    unsigned long long* pq = pSd + kg * 64 + l;
                    pq[0]          = acc00;  pq[32]           = acc10;
                    pq[512]        = acc01;  pq[512 + 32]     = acc11;
                    pq[1024]       = acc02;  pq[1024 + 32]    = acc12;
                    pq[1536]       = acc03;  pq[1536 + 32]    = acc13;
                }
                __syncthreads();

                // ---- layer 3 + epilogue: warp-per-row (warps 0-3) ----
                if (kg < BSUB) {
                    const int r = kg;
                    float acc9[9];
                    #pragma unroll
                    for (int o2 = 0; o2 < 9; ++o2) acc9[o2] = 0.f;
                    #pragma unroll
                    for (int j = 0; j < 2; ++j) {
                        const int slot = 32 * j + l;
                        const unsigned long long* pb = pSd + r * 512 + slot;
                        unsigned long long s0v, s1v, s2v, s3v;
                        ADD2(s0v, pb[0],   pb[64]);
                        ADD2(s1v, pb[128], pb[192]);
                        ADD2(s2v, pb[256], pb[320]);
                        ADD2(s3v, pb[384], pb[448]);
                        ADD2(s0v, s0v, s1v);
                        ADD2(s2v, s2v, s3v);
                        ADD2(s0v, s0v, s2v);
                        ADD2(s0v, s0v, b2d[slot]);
                        float lo, hi; UNPACK2(lo, hi, s0v);
                        float hA = tanha(lo);          // h2[k = slot]
                        float hB = tanha(hi);          // h2[k = slot + 64]
                        const float* wA = W3t + slot * 9;
                        const float* wB = W3t + (slot + 64) * 9;
                        #pragma unroll
                        for (int o2 = 0; o2 < 9; ++o2)
                            acc9[o2] += hA * wA[o2] + hB * wB[o2];
                    }
                    #pragma unroll
                    for (int off = 16; off > 0; off >>= 1) {
                        #pragma unroll
                        for (int o2 = 0; o2 < 9; ++o2)
                            acc9[o2] += __shfl_xor_sync(0xffffffffu, acc9[o2], off);
                    }
                    // epilogue — state lives in lane registers
                    float wgt = dtf * (1.f / 6.f) * Wc[s];
                    if (l < 9) {
                        float a = acc9[l] + b3s[l];
                        if (l == 0) a = -__cosf(a);
                        if (tt > tendr) a = 0.f;
                        Yacc_l = fmaf(wgt, a, Yacc_l);
                        float ynext;
                        if (s < 3) {
                            ynext = fmaf(A2[s + 1] * dtf, a, Ybase_l);
                        } else {
                            Ybase_l = Yacc_l;          // commit substep
                            ynext = Yacc_l;
                        }
                        Ystage[r * 12 + l] = ynext;
                    }
                    if (l == 16) {
                        float tn = tstart + ((s >= 2) ? 1.f : 0.5f) * dtf;
                        cS[r] = interp_c(tn, csS + r * DD);
                    }
                    if (s == 3 && sub == 1 && l == 0)
                        out[(r0 + r) * TT + n + 1] = Ybase_l;
                }
                __syncthreads();
            } // s
        } // sub
    } // n
}

extern "C" void kernel_launch(void* const* d_in, const int* in_sizes, int n_in,
                              void* d_out, int out_size) {
    const float* ts     = (const float*)d_in[0];
    const float* y0     = (const float*)d_in[1];
    const float* latent = (const float*)d_in[2];
    const int*   length = (const int*)  d_in[3];
    const float* dts    = (const float*)d_in[4];
    const float* dcs    = (const float*)d_in[5];
    const float* W1     = (const float*)d_in[6];
    const float* b1     = (const float*)d_in[7];
    const float* W2     = (const float*)d_in[8];
    const float* b2     = (const float*)d_in[9];
    const float* W3     = (const float*)d_in[10];
    const float* b3     = (const float*)d_in[11];
    float* out = (float*)d_out;

    // floats: h1d 1024 + pSd 4096 + b2d 128 + W3t 1152 + csS 1024 + tsS 128
    //         + Ystage 48 + cS 4 + b3s 12  = 7616  (30464 B)
    const size_t smem = 7616 * sizeof(float);
    cudaFuncSetAttribute(ode_kernel, cudaFuncAttributeMaxDynamicSharedMemorySize, (int)smem);

    ode_kernel<<<256, NT, smem>>>(ts, y0, latent, length, dts, dcs,
                                  W1, b1, W2, b2, W3, b3, out);
}

// round 9
// speedup vs baseline: 1.0363x; 1.0363x over previous
#include <cuda_runtime.h>
#include <math.h>

#define NT   256   // 8 warps; L2 thread = (og 0..31, kg 0..7)
#define BSUB 4     // batch rows per CTA
#define TT   128
#define DD   256
#define HW   128
#define HTS  12    // h1t stride in floats

__device__ __forceinline__ float tanha(float x) {
    float y; asm("tanh.approx.f32 %0, %1;" : "=f"(y) : "f"(x)); return y;
}
#define FFMA2(acc, a, b) \
    asm("fma.rn.f32x2 %0, %1, %2, %3;" : "=l"(acc) : "l"(a), "l"(b), "l"(acc))
#define PACK2(d, lo, hi) \
    asm("mov.b64 %0, {%1,%2};" : "=l"(d) : "f"(lo), "f"(hi))
#define UNPACK2(lo, hi, d) \
    asm("mov.b64 {%0,%1}, %2;" : "=f"(lo), "=f"(hi) : "l"(d))

__device__ __forceinline__ float interp_c(float t, const float* __restrict__ row) {
    int i = (int)ceilf(t);
    i = i < 1 ? 1 : (i > DD - 1 ? DD - 1 : i);
    float w = t - (float)(i - 1);
    w = fminf(fmaxf(w, 0.f), 1.f);
    return (1.f - w) * row[i - 1] + w * row[i];
}

__global__ __launch_bounds__(NT, 2)
void ode_kernel(const float* __restrict__ ts, const float* __restrict__ y0,
                const float* __restrict__ latent, const int* __restrict__ length,
                const float* __restrict__ dts, const float* __restrict__ dcs,
                const float* __restrict__ W1, const float* __restrict__ b1,
                const float* __restrict__ W2, const float* __restrict__ b2,
                const float* __restrict__ W3, const float* __restrict__ b3,
                float* __restrict__ out)
{
    extern __shared__ float sm[];
    float* W3t    = sm;                   // [128][9]
    float* h1t    = W3t + 1152;           // [128][12]  h1t[k][r], r<4
    float* pSf    = h1t + HW * HTS;       // 4096 f (u64 o-pair partials)
    float* bpre   = pSf + 4096;           // [4][128]
    float* csS    = bpre + BSUB * HW;     // [4][256]
    float* tsS    = csS + BSUB * DD;      // [128]
    float* b2s    = tsS + TT;             // [128]
    float* Ystage = b2s + HW;             // [4][12]
    float* cS     = Ystage + BSUB * 12;   // [4]
    float* b3s    = cS + 4;               // [12]
    unsigned long long* pS = reinterpret_cast<unsigned long long*>(pSf);

    const int tid = threadIdx.x;
    const int og  = tid & 31;             // lane
    const int kg  = tid >> 5;             // warp 0..7 (k-group)
    const int r0  = blockIdx.x * BSUB;

    const int o1 = og + 32 * (kg & 3);    // L1 neuron
    const int e  = kg >> 2;               // L1 row-pair (rows 2e, 2e+1)

    // ---- one-time setup ----
    for (int i = tid; i < 9 * HW; i += NT) {
        int oo = i >> 7, k = i & 127;
        W3t[k * 9 + oo] = W3[i];
    }
    for (int i = tid; i < BSUB * DD; i += NT) {
        int r = i >> 8;
        csS[i] = dcs[(r0 + r) * DD + (i & 255)];
    }
    if (tid < TT) tsS[tid] = ts[tid];
    if (tid >= 128) b2s[tid - 128] = b2[tid - 128];
    if (tid < 9)  b3s[tid] = b3[tid];

    // ---- register-resident weights (identical to R7) ----
    float w2s[4][16];
    #pragma unroll
    for (int m = 0; m < 4; ++m) {
        const float* wr = W2 + (og + 32 * m) * HW + 16 * kg;
        #pragma unroll
        for (int kk = 0; kk < 16; ++kk) w2s[m][kk] = wr[kk];
    }
    unsigned long long w1p[5];
    float w1t, w1c;
    {
        const float* w = W1 + o1 * 43;
        PACK2(w1p[0], w[0], w[1]);
        PACK2(w1p[1], w[2], w[3]);
        PACK2(w1p[2], w[4], w[5]);
        PACK2(w1p[3], w[6], w[7]);
        PACK2(w1p[4], w[8], 0.f);
        w1t = w[41];
        w1c = w[42];
        float bb = b1[o1];
        #pragma unroll
        for (int rr = 0; rr < 2; ++rr) {
            int r = 2 * e + rr;
            float a = bb;
            const float* lat = latent + (r0 + r) * 32;
            #pragma unroll
            for (int j = 0; j < 32; ++j) a += w[9 + j] * lat[j];
            bpre[r * HW + o1] = a;
        }
    }

    // ---- ODE state in L3-warp lane registers ----
    float Ybase_l = 0.f, Yacc_l = 0.f, tendr = 0.f;
    if (kg < BSUB) {
        const int r = kg;
        int len = length[r0 + r];
        int idx = len - 1; if (idx < 0) idx = 0;
        tendr = ts[idx];
        float y0r = y0[r0 + r];
        if (og == 0) out[(r0 + r) * TT] = y0r;
        if (og < 9) {
            Ybase_l = (og == 0) ? y0r : 0.f;
            Yacc_l  = Ybase_l;
            Ystage[r * 12 + og] = Ybase_l;
        }
        if (og == 16) cS[r] = interp_c(ts[0], dcs + (r0 + r) * DD);
    }
    __syncthreads();

    const float A[4]  = {0.f, 0.5f, 0.5f, 1.f};
    const float Wc[4] = {1.f, 2.f, 2.f, 1.f};
    const int l = og;

    for (int n = 0; n < TT - 1; ++n) {
        float t0  = tsS[n];
        float dtf = (tsS[n + 1] - t0) * 0.5f;     // SUB = 2
        #pragma unroll 1
        for (int sub = 0; sub < 2; ++sub) {
            float tstart = t0 + (float)sub * dtf;
            #pragma unroll
            for (int s = 0; s < 4; ++s) {
                float tt  = tstart + A[s] * dtf;
                float wgt = dtf * (1.f / 6.f) * Wc[s];

                // ---- layer 1: neuron o1, rows 2e,2e+1; store transposed (R7) ----
                {
                    float h2v[2];
                    #pragma unroll
                    for (int rr = 0; rr < 2; ++rr) {
                        const int r = 2 * e + rr;
                        float base = bpre[r * HW + o1] + w1t * tt + w1c * cS[r];
                        ulonglong2 ya = *reinterpret_cast<const ulonglong2*>(Ystage + r * 12);
                        ulonglong2 yb = *reinterpret_cast<const ulonglong2*>(Ystage + r * 12 + 4);
                        unsigned long long y8p;
                        PACK2(y8p, Ystage[r * 12 + 8], 0.f);
                        unsigned long long a2 = 0ull;
                        FFMA2(a2, w1p[0], ya.x);
                        FFMA2(a2, w1p[1], ya.y);
                        FFMA2(a2, w1p[2], yb.x);
                        FFMA2(a2, w1p[3], yb.y);
                        FFMA2(a2, w1p[4], y8p);
                        float lo, hi; UNPACK2(lo, hi, a2);
                        h2v[rr] = tanha(base + lo + hi);
                    }
                    unsigned long long hp; PACK2(hp, h2v[0], h2v[1]);
                    *reinterpret_cast<unsigned long long*>(h1t + o1 * HTS + 2 * e) = hp;
                }
                __syncthreads();

                // ---- layer 2: 4 o x 16 k x 4 rows register tile (R7) ----
                {
                    unsigned long long acc[4][2];
                    #pragma unroll
                    for (int m = 0; m < 4; ++m) { acc[m][0] = 0ull; acc[m][1] = 0ull; }
                    const float* hk = h1t + 16 * kg * HTS;
                    #pragma unroll 4
                    for (int kk = 0; kk < 16; ++kk) {
                        ulonglong2 hv = *reinterpret_cast<const ulonglong2*>(hk + kk * HTS);
                        #pragma unroll
                        for (int m = 0; m < 4; ++m) {
                            unsigned long long wrep;
                            PACK2(wrep, w2s[m][kk], w2s[m][kk]);
                            FFMA2(acc[m][0], wrep, hv.x);
                            FFMA2(acc[m][1], wrep, hv.y);
                        }
                    }
                    #pragma unroll
                    for (int m = 0; m < 4; ++m) {
                        int o = og + 32 * m;
                        pS[kg * 128 + o]        = acc[m][0];
                        pS[1024 + kg * 128 + o] = acc[m][1];
                    }
                }
                __syncthreads();

                // ---- layer 3 + epilogue (state in regs): warps 0-3 ----
                if (kg < BSUB) {
                    const int r = kg;
                    const int rp = r >> 1, rh = r & 1;
                    float acc9[9];
                    #pragma unroll
                    for (int o2 = 0; o2 < 9; ++o2) acc9[o2] = 0.f;
                    const float* pbase = pSf + rp * 2048 + rh;
                    #pragma unroll
                    for (int j = 0; j < 4; ++j) {
                        int k = 32 * j + l;
                        float v = b2s[k];
                        #pragma unroll
                        for (int g = 0; g < 8; ++g)
                            v += pbase[g * 256 + 2 * k];
                        float hh = tanha(v);
                        #pragma unroll
                        for (int o2 = 0; o2 < 9; ++o2)
                            acc9[o2] += hh * W3t[k * 9 + o2];
                    }
                    #pragma unroll
                    for (int off = 16; off > 0; off >>= 1) {
                        #pragma unroll
                        for (int o2 = 0; o2 < 9; ++o2)
                            acc9[o2] += __shfl_xor_sync(0xffffffffu, acc9[o2], off);
                    }
                    if (l < 9) {
                        float a = acc9[l] + b3s[l];
                        if (l == 0) a = -__cosf(a);
                        if (tt > tendr) a = 0.f;
                        Yacc_l = fmaf(wgt, a, Yacc_l);
                        float ynext;
                        if (s < 3) {
                            ynext = fmaf(A[s + 1] * dtf, a, Ybase_l);
                        } else {
                            Ybase_l = Yacc_l;              // substep commit
                            ynext = Yacc_l;
                        }
                        Ystage[r * 12 + l] = ynext;
                    }
                    if (l == 16) {
                        float tn = tstart + ((s >= 2) ? 1.f : 0.5f) * dtf;
                        cS[r] = interp_c(tn, csS + r * DD);
                    }
                    if (s == 3 && sub == 1 && l == 0)
                        out[(r0 + r) * TT + n + 1] = Ybase_l;
                }
                __syncthreads();
            } // s
        } // sub
    } // n
}

extern "C" void kernel_launch(void* const* d_in, const int* in_sizes, int n_in,
                              void* d_out, int out_size) {
    const float* ts     = (const float*)d_in[0];
    const float* y0     = (const float*)d_in[1];
    const float* latent = (const float*)d_in[2];
    const int*   length = (const int*)  d_in[3];
    const float* dts    = (const float*)d_in[4];
    const float* dcs    = (const float*)d_in[5];
    const float* W1     = (const float*)d_in[6];
    const float* b1     = (const float*)d_in[7];
    const float* W2     = (const float*)d_in[8];
    const float* b2     = (const float*)d_in[9];
    const float* W3     = (const float*)d_in[10];
    const float* b3     = (const float*)d_in[11];
    float* out = (float*)d_out;

    // floats: W3t 1152 + h1t 1536 + pSf 4096 + bpre 512 + csS 1024 + tsS 128
    //         + b2s 128 + Ystage 48 + cS 4 + b3s 12 = 8640 (34560 B)
    const size_t smem = 8640 * sizeof(float);
    cudaFuncSetAttribute(ode_kernel, cudaFuncAttributeMaxDynamicSharedMemorySize, (int)smem);

    ode_kernel<<<256, NT, smem>>>(ts, y0, latent, length, dts, dcs,
                                  W1, b1, W2, b2, W3, b3, out);
}

// round 11
// speedup vs baseline: 1.0417x; 1.0051x over previous
#include <cuda_runtime.h>
#include <math.h>

#define NT   256   // 8 warps; L2 thread = (og 0..31, kg 0..7)
#define BSUB 4     // batch rows per CTA
#define TT   128
#define DD   256
#define HW   128

__device__ __forceinline__ float tanha(float x) {
    float y; asm("tanh.approx.f32 %0, %1;" : "=f"(y) : "f"(x)); return y;
}
#define FFMA2(acc, a, b) \
    asm("fma.rn.f32x2 %0, %1, %2, %3;" : "=l"(acc) : "l"(a), "l"(b), "l"(acc))
#define PACK2(d, lo, hi) \
    asm("mov.b64 %0, {%1,%2};" : "=l"(d) : "f"(lo), "f"(hi))
#define UNPACK2(lo, hi, d) \
    asm("mov.b64 {%0,%1}, %2;" : "=f"(lo), "=f"(hi) : "l"(d))
#define BARH(id) \
    asm volatile("bar.sync %0, 128;" :: "r"(id) : "memory")

__device__ __forceinline__ float interp_c(float t, const float* __restrict__ row) {
    int i = (int)ceilf(t);
    i = i < 1 ? 1 : (i > DD - 1 ? DD - 1 : i);
    float w = t - (float)(i - 1);
    w = fminf(fmaxf(w, 0.f), 1.f);
    return (1.f - w) * row[i - 1] + w * row[i];
}

__global__ __launch_bounds__(NT, 2)
void ode_kernel(const float* __restrict__ ts, const float* __restrict__ y0,
                const float* __restrict__ latent, const int* __restrict__ length,
                const float* __restrict__ dts, const float* __restrict__ dcs,
                const float* __restrict__ W1, const float* __restrict__ b1,
                const float* __restrict__ W2, const float* __restrict__ b2,
                const float* __restrict__ W3, const float* __restrict__ b3,
                float* __restrict__ out)
{
    extern __shared__ float sm[];
    float* W3t    = sm;                   // [128][9]  W3t[k*9+o2]
    unsigned long long* h1d = reinterpret_cast<unsigned long long*>(W3t + 1152);
                                          // [2][128] u64: (row2p, row2p+1) per k
    float* pSr    = reinterpret_cast<float*>(h1d + 256); // [4 r][8 kg][128]
    float* bpre   = pSr + 4096;           // [4][128]
    float* csS    = bpre + BSUB * HW;     // [4][256]
    float* tsS    = csS + BSUB * DD;      // [128]
    float* b2s    = tsS + TT;             // [128]
    float* Ystage = b2s + HW;             // [4][12]
    float* cS     = Ystage + BSUB * 12;   // [4]
    float* b3s    = cS + 4;               // [12]

    const int tid = threadIdx.x;
    const int og  = tid & 31;             // lane
    const int kg  = tid >> 5;             // warp 0..7
    const int r0  = blockIdx.x * BSUB;

    const int o1 = og + 32 * (kg & 3);    // L1 neuron
    const int e  = kg >> 2;               // L1 row-pair (rows 2e, 2e+1)
    const bool isL3 = ((kg & 2) == 0);    // warps 0,1,4,5
    const int l3row = (kg & 1) | ((kg >> 1) & 2);  // 0,1,4,5 -> 0,1,2,3

    // ---- one-time setup ----
    for (int i = tid; i < 9 * HW; i += NT) {
        int oo = i >> 7, k = i & 127;
        W3t[k * 9 + oo] = W3[i];
    }
    for (int i = tid; i < BSUB * DD; i += NT) {
        int r = i >> 8;
        csS[i] = dcs[(r0 + r) * DD + (i & 255)];
    }
    if (tid < TT) tsS[tid] = ts[tid];
    if (tid >= 128) b2s[tid - 128] = b2[tid - 128];
    if (tid < 9)  b3s[tid] = b3[tid];

    // ---- register-resident weights ----
    float w2s[4][16];
    #pragma unroll
    for (int m = 0; m < 4; ++m) {
        const float* wr = W2 + (og + 32 * m) * HW + 16 * kg;
        #pragma unroll
        for (int kk = 0; kk < 16; ++kk) w2s[m][kk] = wr[kk];
    }
    unsigned long long w1p[5];
    float w1t, w1c;
    {
        const float* w = W1 + o1 * 43;
        PACK2(w1p[0], w[0], w[1]);
        PACK2(w1p[1], w[2], w[3]);
        PACK2(w1p[2], w[4], w[5]);
        PACK2(w1p[3], w[6], w[7]);
        PACK2(w1p[4], w[8], 0.f);
        w1t = w[41];
        w1c = w[42];
        float bb = b1[o1];
        #pragma unroll
        for (int rr = 0; rr < 2; ++rr) {
            int r = 2 * e + rr;
            float a = bb;
            const float* lat = latent + (r0 + r) * 32;
            #pragma unroll
            for (int j = 0; j < 32; ++j) a += w[9 + j] * lat[j];
            bpre[r * HW + o1] = a;
        }
    }

    // ---- ODE state in L3-warp lane registers ----
    float Ybase_l = 0.f, Yacc_l = 0.f, tendr = 0.f;
    if (isL3) {
        const int r = l3row;
        int len = length[r0 + r];
        int idx = len - 1; if (idx < 0) idx = 0;
        tendr = ts[idx];
        float y0r = y0[r0 + r];
        if (og == 0) out[(r0 + r) * TT] = y0r;
        if (og < 9) {
            Ybase_l = (og == 0) ? y0r : 0.f;
            Yacc_l  = Ybase_l;
            Ystage[r * 12 + og] = Ybase_l;
        }
        if (og == 16) cS[r] = interp_c(ts[0], dcs + (r0 + r) * DD);
    }
    __syncthreads();

    const float A[4]  = {0.f, 0.5f, 0.5f, 1.f};
    const float Wc[4] = {1.f, 2.f, 2.f, 1.f};
    const int l = og;

    for (int n = 0; n < TT - 1; ++n) {
        float t0  = tsS[n];
        float dtf = (tsS[n + 1] - t0) * 0.5f;     // SUB = 2
        #pragma unroll 1
        for (int sub = 0; sub < 2; ++sub) {
            float tstart = t0 + (float)sub * dtf;
            #pragma unroll
            for (int s = 0; s < 4; ++s) {
                float tt  = tstart + A[s] * dtf;
                float wgt = dtf * (1.f / 6.f) * Wc[s];

                // ---- layer 1: neuron o1, rows 2e,2e+1; coalesced pair store ----
                {
                    float h2v[2];
                    #pragma unroll
                    for (int rr = 0; rr < 2; ++rr) {
                        const int r = 2 * e + rr;
                        float base = bpre[r * HW + o1] + w1t * tt + w1c * cS[r];
                        ulonglong2 ya = *reinterpret_cast<const ulonglong2*>(Ystage + r * 12);
                        ulonglong2 yb = *reinterpret_cast<const ulonglong2*>(Ystage + r * 12 + 4);
                        unsigned long long y8p;
                        PACK2(y8p, Ystage[r * 12 + 8], 0.f);
                        unsigned long long a2 = 0ull;
                        FFMA2(a2, w1p[0], ya.x);
                        FFMA2(a2, w1p[1], ya.y);
                        FFMA2(a2, w1p[2], yb.x);
                        FFMA2(a2, w1p[3], yb.y);
                        FFMA2(a2, w1p[4], y8p);
                        float lo, hi; UNPACK2(lo, hi, a2);
                        h2v[rr] = tanha(base + lo + hi);
                    }
                    unsigned long long hp; PACK2(hp, h2v[0], h2v[1]);
                    h1d[e * 128 + o1] = hp;        // coalesced STS.64
                }
                __syncthreads();

                // ---- layer 2: 4 o x 16 k x 4 rows; broadcast LDS.128 k-pairs ----
                {
                    unsigned long long acc[4][2];
                    #pragma unroll
                    for (int m = 0; m < 4; ++m) { acc[m][0] = 0ull; acc[m][1] = 0ull; }
                    const int kbase = 16 * kg;
                    #pragma unroll 4
                    for (int kk = 0; kk < 8; ++kk) {
                        const int k = kbase + 2 * kk;
                        ulonglong2 va = *reinterpret_cast<const ulonglong2*>(h1d + k);        // rows 0,1 | k,k+1
                        ulonglong2 vb = *reinterpret_cast<const ulonglong2*>(h1d + 128 + k);  // rows 2,3 | k,k+1
                        #pragma unroll
                        for (int m = 0; m < 4; ++m) {
                            unsigned long long wa, wb;
                            PACK2(wa, w2s[m][2 * kk],     w2s[m][2 * kk]);
                            PACK2(wb, w2s[m][2 * kk + 1], w2s[m][2 * kk + 1]);
                            FFMA2(acc[m][0], wa, va.x);
                            FFMA2(acc[m][1], wa, vb.x);
                            FFMA2(acc[m][0], wb, va.y);
                            FFMA2(acc[m][1], wb, vb.y);
                        }
                    }
                    // pSr[r][kg][o] — coalesced STS.32
                    #pragma unroll
                    for (int m = 0; m < 4; ++m) {
                        const int o = og + 32 * m;
                        float lo, hi;
                        UNPACK2(lo, hi, acc[m][0]);
                        pSr[kg * 128 + o]        = lo;   // row 0
                        pSr[1024 + kg * 128 + o] = hi;   // row 1
                        UNPACK2(lo, hi, acc[m][1]);
                        pSr[2048 + kg * 128 + o] = lo;   // row 2
                        pSr[3072 + kg * 128 + o] = hi;   // row 3
                    }
                }
                __syncthreads();

                // ---- layer 3 + epilogue: warps 0,1,4,5; xor-butterfly reduce ----
                if (isL3) {
                    const int r = l3row;
                    float acc9[9];
                    #pragma unroll
                    for (int o2 = 0; o2 < 9; ++o2) acc9[o2] = 0.f;
                    const float* pb = pSr + r * 1024;
                    #pragma unroll
                    for (int j = 0; j < 4; ++j) {
                        const int k = 32 * j + l;
                        float p0 = pb[k]       + pb[128 + k];
                        float p1 = pb[256 + k] + pb[384 + k];
                        float p2 = pb[512 + k] + pb[640 + k];
                        float p3 = pb[768 + k] + pb[896 + k];
                        float v = ((p0 + p1) + (p2 + p3)) + b2s[k];
                        float hh = tanha(v);
                        const float* wk = W3t + k * 9;
                        #pragma unroll
                        for (int o2 = 0; o2 < 9; ++o2)
                            acc9[o2] += hh * wk[o2];
                    }
                    #pragma unroll
                    for (int off = 16; off > 0; off >>= 1) {
                        #pragma unroll
                        for (int o2 = 0; o2 < 9; ++o2)
                            acc9[o2] += __shfl_xor_sync(0xffffffffu, acc9[o2], off);
                    }
                    if (l < 9) {
                        float a = acc9[l] + b3s[l];
                        if (l == 0) a = -__cosf(a);
                        if (tt > tendr) a = 0.f;
                        Yacc_l = fmaf(wgt, a, Yacc_l);
                        float ynext;
                        if (s < 3) {
                            ynext = fmaf(A[s + 1] * dtf, a, Ybase_l);
                        } else {
                            Ybase_l = Yacc_l;              // substep commit
                            ynext = Yacc_l;
                        }
                        Ystage[r * 12 + l] = ynext;
                    }
                    if (l == 16) {
                        float tn = tstart + ((s >= 2) ? 1.f : 0.5f) * dtf;
                        cS[r] = interp_c(tn, csS + r * DD);
                    }
                    if (s == 3 && sub == 1 && l == 0)
                        out[(r0 + r) * TT + n + 1] = Ybase_l;
                }
                // half-CTA barriers: A = warps 0-3 (rows 0,1), B = warps 4-7 (rows 2,3)
                if (kg < 4) BARH(1); else BARH(2);
            } // s
        } // sub
    } // n
}

extern "C" void kernel_launch(void* const* d_in, const int* in_sizes, int n_in,
                              void* d_out, int out_size) {
    const float* ts     = (const float*)d_in[0];
    const float* y0     = (const float*)d_in[1];
    const float* latent = (const float*)d_in[2];
    const int*   length = (const int*)  d_in[3];
    const float* dts    = (const float*)d_in[4];
    const float* dcs    = (const float*)d_in[5];
    const float* W1     = (const float*)d_in[6];
    const float* b1     = (const float*)d_in[7];
    const float* W2     = (const float*)d_in[8];
    const float* b2     = (const float*)d_in[9];
    const float* W3     = (const float*)d_in[10];
    const float* b3     = (const float*)d_in[11];
    float* out = (float*)d_out;

    // floats: W3t 1152 + h1d 512 + pSr 4096 + bpre 512 + csS 1024 + tsS 128
    //         + b2s 128 + Ystage 48 + cS 4 + b3s 12 = 7616 (30464 B)
    const size_t smem = 7616 * sizeof(float);
    cudaFuncSetAttribute(ode_kernel, cudaFuncAttributeMaxDynamicSharedMemorySize, (int)smem);

    ode_kernel<<<256, NT, smem>>>(ts, y0, latent, length, dts, dcs,
                                  W1, b1, W2, b2, W3, b3, out);
}

// round 12
// speedup vs baseline: 1.3754x; 1.3204x over previous
#include <cuda_runtime.h>
#include <math.h>

#define NT   256   // 8 warps; warps 0-3 are also row-warps
#define BSUB 4
#define TT   128
#define DD   256
#define HW   128
#define NSTG 1016  // (TT-1)*2*4

__device__ __forceinline__ float tanha(float x) {
    float y; asm("tanh.approx.f32 %0, %1;" : "=f"(y) : "f"(x)); return y;
}
#define FFMA2(acc, a, b) \
    asm("fma.rn.f32x2 %0, %1, %2, %3;" : "=l"(acc) : "l"(a), "l"(b), "l"(acc))
#define PACK2(d, lo, hi) \
    asm("mov.b64 %0, {%1,%2};" : "=l"(d) : "f"(lo), "f"(hi))
#define UNPACK2(lo, hi, d) \
    asm("mov.b64 {%0,%1}, %2;" : "=f"(lo), "=f"(hi) : "l"(d))

__device__ __forceinline__ float interp_c(float t, const float* __restrict__ row) {
    int i = (int)ceilf(t);
    i = i < 1 ? 1 : (i > DD - 1 ? DD - 1 : i);
    float w = t - (float)(i - 1);
    w = fminf(fmaxf(w, 0.f), 1.f);
    return (1.f - w) * row[i - 1] + w * row[i];
}

__global__ __launch_bounds__(NT, 2)
void ode_kernel(const float* __restrict__ ts, const float* __restrict__ y0,
                const float* __restrict__ latent, const int* __restrict__ length,
                const float* __restrict__ dts, const float* __restrict__ dcs,
                const float* __restrict__ W1, const float* __restrict__ b1,
                const float* __restrict__ W2, const float* __restrict__ b2,
                const float* __restrict__ W3, const float* __restrict__ b3,
                float* __restrict__ out)
{
    extern __shared__ float sm[];
    float* W3t = sm;                      // [128][9]
    float* h1r = W3t + 1152;              // [4][128]
    float* pSr = h1r + 512;               // [4 r][8 kg][128 o]
    float* csS = pSr + 4096;              // [4][256]
    float* tsS = csS + 1024;              // [128]
    float* b2s = tsS + 128;               // [128]
    float* b3s = b2s + 128;               // [12], +4 pad -> 7056
    unsigned long long* w1s = reinterpret_cast<unsigned long long*>(sm + 7056); // [20][32]
    unsigned long long* wcb = w1s + 640;  // [4 r][4 nn][32]

    const int tid = threadIdx.x;
    const int l   = tid & 31;
    const int kg  = tid >> 5;             // warp id; also k-slice for L2
    const int r0  = blockIdx.x * BSUB;
    const bool isRow = (kg < BSUB);       // warps 0-3 own rows 0-3

    // ---- one-time setup ----
    for (int i = tid; i < 9 * HW; i += NT) {
        int oo = i >> 7, k = i & 127;
        W3t[k * 9 + oo] = W3[i];
    }
    for (int i = tid; i < BSUB * DD; i += NT) {
        int r = i >> 8;
        csS[i] = dcs[(r0 + r) * DD + (i & 255)];
    }
    if (tid < TT) tsS[tid] = ts[tid];
    if (tid >= 128) b2s[tid - 128] = b2[tid - 128];
    if (tid < 9)  b3s[tid] = b3[tid];

    // w1s[(nn*5+j)][ll]: packed pairs for neuron o=4*ll+nn
    for (int i = tid; i < 640; i += NT) {
        int row = i >> 5, ll = i & 31;
        int nn = row / 5, j = row - nn * 5;
        int o = 4 * ll + nn;
        const float* w = W1 + o * 43;
        float lo, hi;
        if (j < 4) { lo = w[2 * j]; hi = w[2 * j + 1]; }
        else       { lo = w[8];     hi = w[41]; }     // (y8, t)
        unsigned long long p; PACK2(p, lo, hi);
        w1s[row * 32 + ll] = p;
    }
    // wcb[r][nn][ll] = (w_c, b1 + W1[:,9:41]·latent[r])
    for (int i = tid; i < 512; i += NT) {
        int r = i >> 7, nn = (i >> 5) & 3, ll = i & 31;
        int o = 4 * ll + nn;
        const float* w = W1 + o * 43;
        float bp = b1[o];
        const float* lat = latent + (r0 + r) * 32;
        #pragma unroll
        for (int j = 0; j < 32; ++j) bp += w[9 + j] * lat[j];
        unsigned long long p; PACK2(p, w[42], bp);
        wcb[(r * 4 + nn) * 32 + ll] = p;
    }

    // ---- W2 in registers: k-pair packed, all warps ----
    unsigned long long w2p[4][8];         // [m: o=l+32m][kp: k=16kg+2kp]
    #pragma unroll
    for (int m = 0; m < 4; ++m) {
        const float* wr = W2 + (l + 32 * m) * HW + 16 * kg;
        #pragma unroll
        for (int kp = 0; kp < 8; ++kp) PACK2(w2p[m][kp], wr[2 * kp], wr[2 * kp + 1]);
    }

    // ---- replicated ODE state (row warps): 4 u64 + 1 float each ----
    unsigned long long ybase[4], yacc[4], ycur[4];
    float ybase8 = 0.f, yacc8 = 0.f, ycur8 = 0.f, tendr = 0.f;
    #pragma unroll
    for (int j = 0; j < 4; ++j) { ybase[j] = 0ull; yacc[j] = 0ull; ycur[j] = 0ull; }
    if (isRow) {
        const int r = kg;
        int len = length[r0 + r];
        int idx = len - 1; if (idx < 0) idx = 0;
        tendr = ts[idx];
        float y0r = y0[r0 + r];
        if (l == 0) out[(r0 + r) * TT] = y0r;
        PACK2(ybase[0], y0r, 0.f);
        yacc[0] = ybase[0];
        ycur[0] = ybase[0];
    }
    __syncthreads();

    #pragma unroll 1
    for (int g = 0; g < NSTG; ++g) {
        int s = 0, sub = 0, n = 0;
        float dtf = 0.f, tt = 0.f;
        if (isRow) {
            n = g >> 3; sub = (g >> 2) & 1; s = g & 3;
            float t0v = tsS[n];
            dtf = (tsS[n + 1] - t0v) * 0.5f;
            float tstart = t0v + (sub ? dtf : 0.f);
            float As = (s == 0) ? 0.f : ((s == 3) ? 1.f : 0.5f);
            tt = tstart + As * dtf;

            // ---- produce h(g): layer 1 for row kg, 4 neurons/lane ----
            float c = interp_c(tt, csS + kg * DD);
            unsigned long long ytt, c1;
            PACK2(ytt, ycur8, tt);
            PACK2(c1, c, 1.0f);
            float hq[4];
            #pragma unroll
            for (int nn = 0; nn < 4; ++nn) {
                unsigned long long acc = 0ull;
                FFMA2(acc, w1s[(nn * 5 + 0) * 32 + l], ycur[0]);
                FFMA2(acc, w1s[(nn * 5 + 1) * 32 + l], ycur[1]);
                FFMA2(acc, w1s[(nn * 5 + 2) * 32 + l], ycur[2]);
                FFMA2(acc, w1s[(nn * 5 + 3) * 32 + l], ycur[3]);
                FFMA2(acc, w1s[(nn * 5 + 4) * 32 + l], ytt);
                FFMA2(acc, wcb[(kg * 4 + nn) * 32 + l], c1);
                float lo, hi; UNPACK2(lo, hi, acc);
                hq[nn] = tanha(lo + hi);
            }
            *reinterpret_cast<float4*>(h1r + kg * HW + 4 * l) =
                make_float4(hq[0], hq[1], hq[2], hq[3]);
        }
        __syncthreads();

        // ---- layer 2 (all warps): 4 o x 16 k x 4 rows, two row-halves ----
        #pragma unroll
        for (int half = 0; half < 2; ++half) {
            unsigned long long accA[4] = {0ull, 0ull, 0ull, 0ull};
            unsigned long long accB[4] = {0ull, 0ull, 0ull, 0ull};
            const float* ra = h1r + (2 * half) * HW + 16 * kg;
            const float* rb = ra + HW;
            #pragma unroll
            for (int kq = 0; kq < 4; ++kq) {
                ulonglong2 ha = *reinterpret_cast<const ulonglong2*>(ra + 4 * kq);
                ulonglong2 hb = *reinterpret_cast<const ulonglong2*>(rb + 4 * kq);
                #pragma unroll
                for (int m = 0; m < 4; ++m) {
                    FFMA2(accA[m], w2p[m][2 * kq],     ha.x);
                    FFMA2(accA[m], w2p[m][2 * kq + 1], ha.y);
                    FFMA2(accB[m], w2p[m][2 * kq],     hb.x);
                    FFMA2(accB[m], w2p[m][2 * kq + 1], hb.y);
                }
            }
            #pragma unroll
            for (int m = 0; m < 4; ++m) {
                const int o = l + 32 * m;
                float lo, hi;
                UNPACK2(lo, hi, accA[m]);
                pSr[(2 * half) * 1024 + kg * 128 + o] = lo + hi;
                UNPACK2(lo, hi, accB[m]);
                pSr[(2 * half + 1) * 1024 + kg * 128 + o] = lo + hi;
            }
        }
        __syncthreads();

        // ---- consume pS(g): layer 3 + RK4 epilogue, replicated state ----
        if (isRow) {
            const int r = kg;
            float acc9[9];
            #pragma unroll
            for (int o2 = 0; o2 < 9; ++o2) acc9[o2] = 0.f;
            const float* pb = pSr + r * 1024;
            #pragma unroll
            for (int j = 0; j < 4; ++j) {
                const int o = 32 * j + l;
                float p0 = pb[o]       + pb[128 + o];
                float p1 = pb[256 + o] + pb[384 + o];
                float p2 = pb[512 + o] + pb[640 + o];
                float p3 = pb[768 + o] + pb[896 + o];
                float v = ((p0 + p1) + (p2 + p3)) + b2s[o];
                float hh = tanha(v);
                const float* wk = W3t + o * 9;
                #pragma unroll
                for (int o2 = 0; o2 < 9; ++o2)
                    acc9[o2] += hh * wk[o2];
            }
            #pragma unroll
            for (int off = 16; off > 0; off >>= 1) {
                #pragma unroll
                for (int o2 = 0; o2 < 9; ++o2)
                    acc9[o2] += __shfl_xor_sync(0xffffffffu, acc9[o2], off);
            }
            // k-values (replicated on all lanes)
            bool stop = (tt > tendr);
            float kv[9];
            #pragma unroll
            for (int o2 = 0; o2 < 9; ++o2) {
                float a = acc9[o2] + b3s[o2];
                if (o2 == 0) a = -__cosf(a);
                kv[o2] = stop ? 0.f : a;
            }
            float wgt = dtf * (1.f / 6.f) * ((s == 0 || s == 3) ? 1.f : 2.f);
            unsigned long long k01, k23, k45, k67, wg2;
            PACK2(k01, kv[0], kv[1]);
            PACK2(k23, kv[2], kv[3]);
            PACK2(k45, kv[4], kv[5]);
            PACK2(k67, kv[6], kv[7]);
            PACK2(wg2, wgt, wgt);
            FFMA2(yacc[0], wg2, k01);
            FFMA2(yacc[1], wg2, k23);
            FFMA2(yacc[2], wg2, k45);
            FFMA2(yacc[3], wg2, k67);
            yacc8 = fmaf(wgt, kv[8], yacc8);
            if (s < 3) {
                float stg = ((s == 2) ? 1.f : 0.5f) * dtf;
                unsigned long long st2; PACK2(st2, stg, stg);
                ycur[0] = ybase[0]; FFMA2(ycur[0], st2, k01);
                ycur[1] = ybase[1]; FFMA2(ycur[1], st2, k23);
                ycur[2] = ybase[2]; FFMA2(ycur[2], st2, k45);
                ycur[3] = ybase[3]; FFMA2(ycur[3], st2, k67);
                ycur8 = fmaf(stg, kv[8], ybase8);
            } else {
                #pragma unroll
                for (int j = 0; j < 4; ++j) { ybase[j] = yacc[j]; ycur[j] = yacc[j]; }
                ybase8 = yacc8; ycur8 = yacc8;
                if (sub == 1 && l == 0) {
                    float yb, dum; UNPACK2(yb, dum, ybase[0]);
                    out[(r0 + r) * TT + n + 1] = yb;
                }
            }
        }
    } // g
}

extern "C" void kernel_launch(void* const* d_in, const int* in_sizes, int n_in,
                              void* d_out, int out_size) {
    const float* ts     = (const float*)d_in[0];
    const float* y0     = (const float*)d_in[1];
    const float* latent = (const float*)d_in[2];
    const int*   length = (const int*)  d_in[3];
    const float* dts    = (const float*)d_in[4];
    const float* dcs    = (const float*)d_in[5];
    const float* W1     = (const float*)d_in[6];
    const float* b1     = (const float*)d_in[7];
    const float* W2     = (const float*)d_in[8];
    const float* b2     = (const float*)d_in[9];
    const float* W3     = (const float*)d_in[10];
    const float* b3     = (const float*)d_in[11];
    float* out = (float*)d_out;

    // floats: 7056 + w1s 1280 + wcb 1024 = 9360 (37440 B)
    const size_t smem = 9360 * sizeof(float);
    cudaFuncSetAttribute(ode_kernel, cudaFuncAttributeMaxDynamicSharedMemorySize, (int)smem);

    ode_kernel<<<256, NT, smem>>>(ts, y0, latent, length, dts, dcs,
                                  W1, b1, W2, b2, W3, b3, out);
}

// round 13
// speedup vs baseline: 1.5312x; 1.1132x over previous
#include <cuda_runtime.h>
#include <math.h>

#define NT   256
#define BSUB 4
#define TT   128
#define DD   256
#define HW   128
#define NSTG 1016  // (TT-1)*2*4

__device__ __forceinline__ float tanha(float x) {
    float y; asm("tanh.approx.f32 %0, %1;" : "=f"(y) : "f"(x)); return y;
}
#define FFMA2(acc, a, b) \
    asm("fma.rn.f32x2 %0, %1, %2, %3;" : "=l"(acc) : "l"(a), "l"(b), "l"(acc))
#define PACK2(d, lo, hi) \
    asm("mov.b64 %0, {%1,%2};" : "=l"(d) : "f"(lo), "f"(hi))
#define UNPACK2(lo, hi, d) \
    asm("mov.b64 {%0,%1}, %2;" : "=f"(lo), "=f"(hi) : "l"(d))
#define BAR0() asm volatile("bar.sync 0, 256;" ::: "memory")
#define BAR1_SYNC() asm volatile("bar.sync 1, 256;" ::: "memory")
#define BAR1_ARRIVE() asm volatile("bar.arrive 1, 256;" ::: "memory")

__device__ __forceinline__ float interp_c(float t, const float* __restrict__ row) {
    int i = (int)ceilf(t);
    i = i < 1 ? 1 : (i > DD - 1 ? DD - 1 : i);
    float w = t - (float)(i - 1);
    w = fminf(fmaxf(w, 0.f), 1.f);
    return (1.f - w) * row[i - 1] + w * row[i];
}

// L2 partial GEMM over a k-slice of 4*NQ columns, 4 o per thread, 4 rows.
template<int NQ>
__device__ __forceinline__ void l2_slice(
    const unsigned long long (*w2p)[2 * NQ],
    const float* __restrict__ h1r, float* __restrict__ pSr,
    int kg, int kbase, int l)
{
    #pragma unroll
    for (int half = 0; half < 2; ++half) {
        unsigned long long accA[4] = {0ull, 0ull, 0ull, 0ull};
        unsigned long long accB[4] = {0ull, 0ull, 0ull, 0ull};
        const float* ra = h1r + (2 * half) * HW + kbase;
        const float* rb = ra + HW;
        #pragma unroll
        for (int kq = 0; kq < NQ; ++kq) {
            ulonglong2 ha = *reinterpret_cast<const ulonglong2*>(ra + 4 * kq);
            ulonglong2 hb = *reinterpret_cast<const ulonglong2*>(rb + 4 * kq);
            #pragma unroll
            for (int m = 0; m < 4; ++m) {
                FFMA2(accA[m], w2p[m][2 * kq],     ha.x);
                FFMA2(accA[m], w2p[m][2 * kq + 1], ha.y);
                FFMA2(accB[m], w2p[m][2 * kq],     hb.x);
                FFMA2(accB[m], w2p[m][2 * kq + 1], hb.y);
            }
        }
        #pragma unroll
        for (int m = 0; m < 4; ++m) {
            const int o = l + 32 * m;
            float lo, hi;
            UNPACK2(lo, hi, accA[m]);
            pSr[(2 * half) * 1024 + kg * 128 + o] = lo + hi;
            UNPACK2(lo, hi, accB[m]);
            pSr[(2 * half + 1) * 1024 + kg * 128 + o] = lo + hi;
        }
    }
}

__global__ __launch_bounds__(NT, 2)
void ode_kernel(const float* __restrict__ ts, const float* __restrict__ y0,
                const float* __restrict__ latent, const int* __restrict__ length,
                const float* __restrict__ dts, const float* __restrict__ dcs,
                const float* __restrict__ W1, const float* __restrict__ b1,
                const float* __restrict__ W2, const float* __restrict__ b2,
                const float* __restrict__ W3, const float* __restrict__ b3,
                float* __restrict__ out)
{
    extern __shared__ float sm[];
    float* W3t = sm;                      // [128][9]
    float* h1r = W3t + 1152;              // [4][128]
    float* pSr = h1r + 512;               // [4 r][8 kg][128 o]
    float* csS = pSr + 4096;              // [4][256]
    float* tsS = csS + 1024;              // [128]
    float* b2s = tsS + 128;               // [128]
    float* b3s = b2s + 128;               // [12] +4 pad -> 7056
    unsigned long long* w1s = reinterpret_cast<unsigned long long*>(sm + 7056); // [20][32]

    const int tid = threadIdx.x;
    const int l   = tid & 31;
    const int kg  = tid >> 5;
    const int r0  = blockIdx.x * BSUB;

    // ---- one-time setup ----
    for (int i = tid; i < 9 * HW; i += NT) {
        int oo = i >> 7, k = i & 127;
        W3t[k * 9 + oo] = W3[i];
    }
    for (int i = tid; i < BSUB * DD; i += NT) {
        int r = i >> 8;
        csS[i] = dcs[(r0 + r) * DD + (i & 255)];
    }
    if (tid < TT) tsS[tid] = ts[tid];
    if (tid >= 128) b2s[tid - 128] = b2[tid - 128];
    if (tid < 9)  b3s[tid] = b3[tid];
    // w1s[(nn*5+j)][ll]: packed pairs for neuron o = 4*ll+nn
    for (int i = tid; i < 640; i += NT) {
        int row = i >> 5, ll = i & 31;
        int nn = row / 5, j = row - nn * 5;
        int o = 4 * ll + nn;
        const float* w = W1 + o * 43;
        float lo, hi;
        if (j < 4) { lo = w[2 * j]; hi = w[2 * j + 1]; }
        else       { lo = w[8];     hi = w[41]; }     // (y8, t)
        unsigned long long p; PACK2(p, lo, hi);
        w1s[row * 32 + ll] = p;
    }
    __syncthreads();

    if (kg < BSUB) {
        // ================= ROW WARP (warp r = kg) =================
        const int r = kg;
        // L2 slice: 8 k, kbase = 8*kg
        unsigned long long w2p[4][4];
        #pragma unroll
        for (int m = 0; m < 4; ++m) {
            const float* wr = W2 + (l + 32 * m) * HW + 8 * kg;
            #pragma unroll
            for (int kp = 0; kp < 4; ++kp) PACK2(w2p[m][kp], wr[2 * kp], wr[2 * kp + 1]);
        }
        // wcbr[nn] = (w_c, b1 + W1[:,9:41]·latent[r]) for neuron o=4l+nn
        unsigned long long wcbr[4];
        #pragma unroll
        for (int nn = 0; nn < 4; ++nn) {
            int o = 4 * l + nn;
            const float* w = W1 + o * 43;
            float bp = b1[o];
            const float* lat = latent + (r0 + r) * 32;
            #pragma unroll
            for (int j = 0; j < 32; ++j) bp += w[9 + j] * lat[j];
            PACK2(wcbr[nn], w[42], bp);
        }
        // replicated ODE state
        unsigned long long ybase[4], yacc[4], ycur[4];
        #pragma unroll
        for (int j = 0; j < 4; ++j) { ybase[j] = 0ull; yacc[j] = 0ull; ycur[j] = 0ull; }
        float ybase8 = 0.f, yacc8 = 0.f, ycur8 = 0.f;
        int len = length[r0 + r];
        int idx = len - 1; if (idx < 0) idx = 0;
        float tendr = ts[idx];
        float y0r = y0[r0 + r];
        if (l == 0) out[(r0 + r) * TT] = y0r;
        PACK2(ybase[0], y0r, 0.f);
        yacc[0] = ybase[0];
        ycur[0] = ybase[0];

        #pragma unroll 1
        for (int g = 0; g < NSTG; ++g) {
            const int n = g >> 3, sub = (g >> 2) & 1, s = g & 3;
            float t0v = tsS[n];
            float dtf = (tsS[n + 1] - t0v) * 0.5f;
            float tstart = t0v + (sub ? dtf : 0.f);
            float As = (s == 0) ? 0.f : ((s == 3) ? 1.f : 0.5f);
            float tt = tstart + As * dtf;

            // ---- produce h(g): layer 1 for row r, 4 neurons/lane ----
            {
                float c = interp_c(tt, csS + r * DD);
                unsigned long long ytt, c1;
                PACK2(ytt, ycur8, tt);
                PACK2(c1, c, 1.0f);
                float hq[4];
                #pragma unroll
                for (int nn = 0; nn < 4; ++nn) {
                    unsigned long long acc = 0ull;
                    FFMA2(acc, w1s[(nn * 5 + 0) * 32 + l], ycur[0]);
                    FFMA2(acc, w1s[(nn * 5 + 1) * 32 + l], ycur[1]);
                    FFMA2(acc, w1s[(nn * 5 + 2) * 32 + l], ycur[2]);
                    FFMA2(acc, w1s[(nn * 5 + 3) * 32 + l], ycur[3]);
                    FFMA2(acc, w1s[(nn * 5 + 4) * 32 + l], ytt);
                    FFMA2(acc, wcbr[nn], c1);
                    float lo, hi; UNPACK2(lo, hi, acc);
                    hq[nn] = tanha(lo + hi);
                }
                *reinterpret_cast<float4*>(h1r + r * HW + 4 * l) =
                    make_float4(hq[0], hq[1], hq[2], hq[3]);
            }
            BAR0();

            // ---- layer 2 small slice ----
            l2_slice<2>(w2p, h1r, pSr, kg, 8 * kg, l);
            BAR1_SYNC();

            // ---- consume pS(g): layer 3 + RK4 epilogue ----
            {
                float acc9[9];
                #pragma unroll
                for (int o2 = 0; o2 < 9; ++o2) acc9[o2] = 0.f;
                const float* pb = pSr + r * 1024;
                #pragma unroll
                for (int j = 0; j < 4; ++j) {
                    const int o = 32 * j + l;
                    float p0 = pb[o]       + pb[128 + o];
                    float p1 = pb[256 + o] + pb[384 + o];
                    float p2 = pb[512 + o] + pb[640 + o];
                    float p3 = pb[768 + o] + pb[896 + o];
                    float v = ((p0 + p1) + (p2 + p3)) + b2s[o];
                    float hh = tanha(v);
                    const float* wk = W3t + o * 9;
                    #pragma unroll
                    for (int o2 = 0; o2 < 9; ++o2)
                        acc9[o2] += hh * wk[o2];
                }
                #pragma unroll
                for (int off = 16; off > 0; off >>= 1) {
                    #pragma unroll
                    for (int o2 = 0; o2 < 9; ++o2)
                        acc9[o2] += __shfl_xor_sync(0xffffffffu, acc9[o2], off);
                }
                bool stop = (tt > tendr);
                float kv[9];
                #pragma unroll
                for (int o2 = 0; o2 < 9; ++o2) {
                    float a = acc9[o2] + b3s[o2];
                    if (o2 == 0) a = -__cosf(a);
                    kv[o2] = stop ? 0.f : a;
                }
                float wgt = dtf * (1.f / 6.f) * ((s == 0 || s == 3) ? 1.f : 2.f);
                unsigned long long k01, k23, k45, k67, wg2;
                PACK2(k01, kv[0], kv[1]);
                PACK2(k23, kv[2], kv[3]);
                PACK2(k45, kv[4], kv[5]);
                PACK2(k67, kv[6], kv[7]);
                PACK2(wg2, wgt, wgt);
                FFMA2(yacc[0], wg2, k01);
                FFMA2(yacc[1], wg2, k23);
                FFMA2(yacc[2], wg2, k45);
                FFMA2(yacc[3], wg2, k67);
                yacc8 = fmaf(wgt, kv[8], yacc8);
                if (s < 3) {
                    float stg = ((s == 2) ? 1.f : 0.5f) * dtf;
                    unsigned long long st2; PACK2(st2, stg, stg);
                    ycur[0] = ybase[0]; FFMA2(ycur[0], st2, k01);
                    ycur[1] = ybase[1]; FFMA2(ycur[1], st2, k23);
                    ycur[2] = ybase[2]; FFMA2(ycur[2], st2, k45);
                    ycur[3] = ybase[3]; FFMA2(ycur[3], st2, k67);
                    ycur8 = fmaf(stg, kv[8], ybase8);
                } else {
                    #pragma unroll
                    for (int j = 0; j < 4; ++j) { ybase[j] = yacc[j]; ycur[j] = yacc[j]; }
                    ybase8 = yacc8; ycur8 = yacc8;
                    if (sub == 1 && l == 0) {
                        float yb, dum; UNPACK2(yb, dum, ybase[0]);
                        out[(r0 + r) * TT + n + 1] = yb;
                    }
                }
            }
        }
    } else {
        // ================= HELPER WARP (kg 4..7) =================
        // L2 slice: 24 k, kbase = 32 + 24*(kg-4)
        const int kbase = 32 + 24 * (kg - 4);
        unsigned long long w2p[4][12];
        #pragma unroll
        for (int m = 0; m < 4; ++m) {
            const float* wr = W2 + (l + 32 * m) * HW + kbase;
            #pragma unroll
            for (int kp = 0; kp < 12; ++kp) PACK2(w2p[m][kp], wr[2 * kp], wr[2 * kp + 1]);
        }
        #pragma unroll 1
        for (int g = 0; g < NSTG; ++g) {
            BAR0();
            l2_slice<6>(w2p, h1r, pSr, kg, kbase, l);
            BAR1_ARRIVE();
        }
    }
}

extern "C" void kernel_launch(void* const* d_in, const int* in_sizes, int n_in,
                              void* d_out, int out_size) {
    const float* ts     = (const float*)d_in[0];
    const float* y0     = (const float*)d_in[1];
    const float* latent = (const float*)d_in[2];
    const int*   length = (const int*)  d_in[3];
    const float* dts    = (const float*)d_in[4];
    const float* dcs    = (const float*)d_in[5];
    const float* W1     = (const float*)d_in[6];
    const float* b1     = (const float*)d_in[7];
    const float* W2     = (const float*)d_in[8];
    const float* b2     = (const float*)d_in[9];
    const float* W3     = (const float*)d_in[10];
    const float* b3     = (const float*)d_in[11];
    float* out = (float*)d_out;

    // floats: 7056 + w1s 1280 = 8336 (33344 B)
    const size_t smem = 8336 * sizeof(float);
    cudaFuncSetAttribute(ode_kernel, cudaFuncAttributeMaxDynamicSharedMemorySize, (int)smem);

    ode_kernel<<<256, NT, smem>>>(ts, y0, latent, length, dts, dcs,
                                  W1, b1, W2, b2, W3, b3, out);
}